// round 2
// baseline (speedup 1.0000x reference)
#include <cuda_runtime.h>

// ---------------------------------------------------------------------------
// weighted_loss: scalar loss over B=4.2M rows, 3 tasks (head/chest/neck).
// Single-launch design: per-block partials + last-block-done final reduction
// (threadfence reduction). No zero/finalize kernels -> saves ~8us of launch
// overhead. Compute path: branchless selects, poly-exp (no MUFU), LUT 1.1^n.
// ---------------------------------------------------------------------------

#define MAX_BLOCKS 8192

__device__ float g_partial[MAX_BLOCKS];
__device__ unsigned int g_ticket = 0;   // always returns to 0 -> deterministic

__device__ __forceinline__ float stepf(float x, float t) {
    return (x >= t) ? 1.0f : 0.0f;
}

// exp(u) for u in [-0.23, 0.7], degree-5 Horner. abs err < 2e-7 on our range.
__device__ __forceinline__ float exp_small(float u) {
    float h = fmaf(u, 8.3333333e-3f, 4.1666668e-2f);  // 1/120, 1/24
    h = fmaf(u, h, 0.16666667f);                       // 1/6
    h = fmaf(u, h, 0.5f);
    h = fmaf(u, h, 1.0f);
    return fmaf(u, h, 1.0f);
}

// |ais(p) - ais(t)| for 5 sorted thresholds
__device__ __forceinline__ float aisdiff5(float p, float t,
                                          float t0, float t1, float t2,
                                          float t3, float t4) {
    float d = stepf(p, t0) - stepf(t, t0);
    d += stepf(p, t1) - stepf(t, t1);
    d += stepf(p, t2) - stepf(t, t2);
    d += stepf(p, t3) - stepf(t, t3);
    d += stepf(p, t4) - stepf(t, t4);
    return fabsf(d);
}

// w_mid = 1 + piecewise_linear(yt, yp), mid = 1.
//   [0,a): 1+yt/a  [a,b]: 2  (b,c): 2-(yt-b)/(c-b)  [c,d]: 1  (d,inf): exp(-k(yt-d))
//   +1 if yp < 0.   C3 = 2 + b*inv_cb ; neg_k = -ln2/d (k*d = ln2).
__device__ __forceinline__ float wmid_f(float yt, float yp,
                                        float a, float b, float c, float d,
                                        float inv_a, float neg_inv_cb,
                                        float C3, float neg_k) {
    float w1m = fmaf(yt, inv_a, 1.0f);
    float w3m = fmaf(yt, neg_inv_cb, C3);
    float u   = fmaf(neg_k, yt, 0.69314718f);   // = -k*(yt-d)
    float e   = exp_small(u);
    float lo  = (yt < a)  ? w1m : 2.0f;
    float hi  = (yt <= d) ? 1.0f : e;
    hi        = (yt < c)  ? w3m : hi;
    float w   = (yt <= b) ? lo : hi;
    w += (yp < 0.0f) ? 1.0f : 0.0f;
    return w;
}

__device__ __forceinline__ float row_loss(const float* __restrict__ sW,
                                          float ph, float pd, float pn,
                                          float th, float td, float tn,
                                          int o) {
    // head: thr {150,500,1000,1800,2600}; a=80 b=1500 c=1750 d=2000
    float dh = aisdiff5(ph, th, 150.0f, 500.0f, 1000.0f, 1800.0f, 2600.0f);
    float mh = wmid_f(th, ph, 80.0f, 1500.0f, 1750.0f, 2000.0f,
                      0.0125f, -0.004f, 8.0f, -3.4657359e-4f);
    float L = fabsf(ph - th) * sW[(int)dh] * mh;

    // chest: thr {22,35,45,55,65} * scale[ot]; a=10 b=75 c=85 d=100
    float s = fmaf(0.1f, (float)o, 0.8f);
    float dc = aisdiff5(pd, td, 22.0f * s, 35.0f * s, 45.0f * s,
                        55.0f * s, 65.0f * s);
    float mc = wmid_f(td, pd, 10.0f, 75.0f, 85.0f, 100.0f,
                      0.1f, -0.1f, 9.5f, -6.9314718e-3f);
    L += fabsf(pd - td) * sW[(int)dc] * mc;

    // neck: thr {0.2,0.5,1.0,1.5,2.0}; a=0.15 b=1.5 c=1.7 d=1.9
    float dn = aisdiff5(pn, tn, 0.2f, 0.5f, 1.0f, 1.5f, 2.0f);
    float mn = wmid_f(tn, pn, 0.15f, 1.5f, 1.7f, 1.9f,
                      6.6666667f, -5.0f, 9.5f, -0.36481431f);
    L += fabsf(pn - tn) * sW[(int)dn] * mn;

    return L;
}

__global__ void __launch_bounds__(256)
loss_kernel(const float* __restrict__ pred,
            const float* __restrict__ tru,
            const int* __restrict__ ot,
            int ngroups, int nrows,
            float* __restrict__ out, double invN) {
    __shared__ float sW[8];
    __shared__ double warpsumd[8];
    __shared__ float warpsum[8];
    __shared__ int s_islast;
    if (threadIdx.x == 0) {
        sW[0] = 1.0f;    sW[1] = 1.1f;     sW[2] = 1.21f;
        sW[3] = 1.331f;  sW[4] = 1.4641f;  sW[5] = 1.61051f;
    }
    __syncthreads();

    const float4* __restrict__ pv = (const float4*)pred;
    const float4* __restrict__ tv = (const float4*)tru;
    const int4* __restrict__ ov = (const int4*)ot;

    int tid = blockIdx.x * blockDim.x + threadIdx.x;
    int stride = gridDim.x * blockDim.x;

    float acc = 0.0f;
    for (int g = tid; g < ngroups; g += stride) {
        float4 p0 = pv[3 * g + 0];
        float4 p1 = pv[3 * g + 1];
        float4 p2 = pv[3 * g + 2];
        float4 t0 = tv[3 * g + 0];
        float4 t1 = tv[3 * g + 1];
        float4 t2 = tv[3 * g + 2];
        int4 o = ov[g];
        acc += row_loss(sW, p0.x, p0.y, p0.z, t0.x, t0.y, t0.z, o.x);
        acc += row_loss(sW, p0.w, p1.x, p1.y, t0.w, t1.x, t1.y, o.y);
        acc += row_loss(sW, p1.z, p1.w, p2.x, t1.z, t1.w, t2.x, o.z);
        acc += row_loss(sW, p2.y, p2.z, p2.w, t2.y, t2.z, t2.w, o.w);
    }
    // tail rows (B % 4 != 0 — not hit for B=4194304)
    for (int r = 4 * ngroups + tid; r < nrows; r += stride) {
        acc += row_loss(sW, pred[3 * r + 0], pred[3 * r + 1], pred[3 * r + 2],
                        tru[3 * r + 0], tru[3 * r + 1], tru[3 * r + 2], ot[r]);
    }

    // ---- block reduce (fp32) ----
    #pragma unroll
    for (int off = 16; off > 0; off >>= 1)
        acc += __shfl_xor_sync(0xffffffffu, acc, off);

    int lane = threadIdx.x & 31;
    int warp = threadIdx.x >> 5;
    if (lane == 0) warpsum[warp] = acc;
    __syncthreads();

    if (threadIdx.x == 0) {
        float bsum = 0.0f;
        #pragma unroll
        for (int w = 0; w < 8; w++) bsum += warpsum[w];
        g_partial[blockIdx.x] = bsum;
        __threadfence();
        unsigned int v = atomicAdd(&g_ticket, 1u);
        s_islast = (v == gridDim.x - 1) ? 1 : 0;
    }
    __syncthreads();

    // ---- last block finishes: reduce partials in double, write out ----
    if (s_islast) {
        double d = 0.0;
        for (int i = threadIdx.x; i < gridDim.x; i += blockDim.x)
            d += (double)g_partial[i];
        #pragma unroll
        for (int off = 16; off > 0; off >>= 1)
            d += __shfl_xor_sync(0xffffffffu, d, off);
        if (lane == 0) warpsumd[warp] = d;
        __syncthreads();
        if (threadIdx.x == 0) {
            double tot = 0.0;
            #pragma unroll
            for (int w = 0; w < 8; w++) tot += warpsumd[w];
            out[0] = (float)(tot * invN);
            g_ticket = 0;   // reset for next graph replay -> deterministic
        }
    }
}

extern "C" void kernel_launch(void* const* d_in, const int* in_sizes, int n_in,
                              void* d_out, int out_size) {
    const float* pred = (const float*)d_in[0];
    const float* tru  = (const float*)d_in[1];
    const int*   ot   = (const int*)d_in[2];
    float* out = (float*)d_out;

    int B = in_sizes[0] / 3;
    int ngroups = B / 4;

    int threads = 256;
    int blocks = (ngroups + threads - 1) / threads;
    if (blocks < 1) blocks = 1;
    if (blocks > MAX_BLOCKS) blocks = MAX_BLOCKS;

    loss_kernel<<<blocks, threads>>>(pred, tru, ot, ngroups, B, out,
                                     1.0 / (double)B);
}

// round 3
// speedup vs baseline: 1.1106x; 1.1106x over previous
#include <cuda_runtime.h>
#include <cuda_fp16.h>

// ---------------------------------------------------------------------------
// weighted_loss over B=4.2M rows x 3 tasks. Single launch, threadfence
// reduction. AIS threshold counting done in packed half2 (pred,true lanes
// compared simultaneously): 5x HSET2 + 4x HADD2 per task instead of 10x FSETP
// + 10 selects. All-float reduction (no doubles) to keep regs <= 40 for
// 6 CTAs/SM occupancy.
// ---------------------------------------------------------------------------

#define MAX_BLOCKS 8192

__device__ float g_partial[MAX_BLOCKS];
__device__ unsigned int g_ticket = 0;   // returns to 0 each call -> deterministic

// compile-time half2 constant (same value both lanes) from fp16 bit pattern
__device__ __forceinline__ __half2 h2c(unsigned short u) {
    __half2_raw r; r.x = u; r.y = u;
    return *reinterpret_cast<__half2*>(&r);
}

// exp(u) for u in [-0.23, 0.7], degree-5 Horner. abs err < 2e-7 on our range.
__device__ __forceinline__ float exp_small(float u) {
    float h = fmaf(u, 8.3333333e-3f, 4.1666668e-2f);
    h = fmaf(u, h, 0.16666667f);
    h = fmaf(u, h, 0.5f);
    h = fmaf(u, h, 1.0f);
    return fmaf(u, h, 1.0f);
}

// |ais(p)-ais(t)| with (p,t) packed in half2, 5 broadcast-thresholds.
// __hge2 yields 1.0/0.0 per lane; counts are small ints (exact in fp16).
__device__ __forceinline__ float aisdiff5h(__half2 pt, __half2 a0, __half2 a1,
                                           __half2 a2, __half2 a3, __half2 a4) {
    __half2 acc = __hge2(pt, a0);
    acc = __hadd2(acc, __hge2(pt, a1));
    acc = __hadd2(acc, __hge2(pt, a2));
    acc = __hadd2(acc, __hge2(pt, a3));
    acc = __hadd2(acc, __hge2(pt, a4));
    float2 f = __half22float2(acc);
    return fabsf(f.x - f.y);
}

// w_mid = 1 + piecewise_linear(yt, yp), mid = 1 (float-exact boundaries).
__device__ __forceinline__ float wmid_f(float yt, float yp,
                                        float a, float b, float c, float d,
                                        float inv_a, float neg_inv_cb,
                                        float C3, float neg_k) {
    float w1m = fmaf(yt, inv_a, 1.0f);
    float w3m = fmaf(yt, neg_inv_cb, C3);
    float u   = fmaf(neg_k, yt, 0.69314718f);   // = -k*(yt-d), k*d = ln2
    float e   = exp_small(u);
    float lo  = (yt < a)  ? w1m : 2.0f;
    float hi  = (yt <= d) ? 1.0f : e;
    hi        = (yt < c)  ? w3m : hi;
    float w   = (yt <= b) ? lo : hi;
    w += (yp < 0.0f) ? 1.0f : 0.0f;
    return w;
}

__device__ __forceinline__ float row_loss(const float* __restrict__ sW,
                                          float ph, float pd, float pn,
                                          float th, float td, float tn,
                                          int o) {
    // ---- head: thr {150,500,1000,1800,2600} (fp16-exact)
    float dh = aisdiff5h(__floats2half2_rn(ph, th),
                         h2c(0x58B0), h2c(0x5FD0), h2c(0x63D0),
                         h2c(0x6708), h2c(0x6914));
    float mh = wmid_f(th, ph, 80.0f, 1500.0f, 1750.0f, 2000.0f,
                      0.0125f, -0.004f, 8.0f, -3.4657359e-4f);
    float L = fabsf(ph - th) * sW[(int)dh] * mh;

    // ---- chest: thr {22,35,45,55,65} * (0.8 + 0.1*ot)
    float s = fmaf(0.1f, (float)o, 0.8f);
    __half2 s2 = __half2half2(__float2half_rn(s));
    float dc = aisdiff5h(__floats2half2_rn(pd, td),
                         __hmul2(h2c(0x4D80), s2),   // 22*s
                         __hmul2(h2c(0x5060), s2),   // 35*s
                         __hmul2(h2c(0x51A0), s2),   // 45*s
                         __hmul2(h2c(0x52E0), s2),   // 55*s
                         __hmul2(h2c(0x5410), s2));  // 65*s
    float mc = wmid_f(td, pd, 10.0f, 75.0f, 85.0f, 100.0f,
                      0.1f, -0.1f, 9.5f, -6.9314718e-3f);
    L += fabsf(pd - td) * sW[(int)dc] * mc;

    // ---- neck: thr {0.2,0.5,1.0,1.5,2.0}
    float dn = aisdiff5h(__floats2half2_rn(pn, tn),
                         h2c(0x3266), h2c(0x3800), h2c(0x3C00),
                         h2c(0x3E00), h2c(0x4000));
    float mn = wmid_f(tn, pn, 0.15f, 1.5f, 1.7f, 1.9f,
                      6.6666667f, -5.0f, 9.5f, -0.36481431f);
    L += fabsf(pn - tn) * sW[(int)dn] * mn;

    return L;
}

__global__ void __launch_bounds__(256, 6)
loss_kernel(const float* __restrict__ pred,
            const float* __restrict__ tru,
            const int* __restrict__ ot,
            int ngroups, int nrows,
            float* __restrict__ out, float invN) {
    __shared__ float sW[8];
    __shared__ float warpsum[8];
    __shared__ int s_islast;
    if (threadIdx.x == 0) {
        sW[0] = 1.0f;    sW[1] = 1.1f;     sW[2] = 1.21f;
        sW[3] = 1.331f;  sW[4] = 1.4641f;  sW[5] = 1.61051f;
    }
    __syncthreads();

    const float4* __restrict__ pv = (const float4*)pred;
    const float4* __restrict__ tv = (const float4*)tru;
    const int4* __restrict__ ov = (const int4*)ot;

    int tid = blockIdx.x * blockDim.x + threadIdx.x;
    int stride = gridDim.x * blockDim.x;

    float acc = 0.0f;
    for (int g = tid; g < ngroups; g += stride) {
        float4 p0 = pv[3 * g + 0];
        float4 p1 = pv[3 * g + 1];
        float4 p2 = pv[3 * g + 2];
        float4 t0 = tv[3 * g + 0];
        float4 t1 = tv[3 * g + 1];
        float4 t2 = tv[3 * g + 2];
        int4 o = ov[g];
        acc += row_loss(sW, p0.x, p0.y, p0.z, t0.x, t0.y, t0.z, o.x);
        acc += row_loss(sW, p0.w, p1.x, p1.y, t0.w, t1.x, t1.y, o.y);
        acc += row_loss(sW, p1.z, p1.w, p2.x, t1.z, t1.w, t2.x, o.z);
        acc += row_loss(sW, p2.y, p2.z, p2.w, t2.y, t2.z, t2.w, o.w);
    }
    // tail rows (B % 4 != 0 -- not hit for B=4194304)
    for (int r = 4 * ngroups + tid; r < nrows; r += stride) {
        acc += row_loss(sW, pred[3 * r + 0], pred[3 * r + 1], pred[3 * r + 2],
                        tru[3 * r + 0], tru[3 * r + 1], tru[3 * r + 2], ot[r]);
    }

    // ---- block reduce (float) ----
    #pragma unroll
    for (int off = 16; off > 0; off >>= 1)
        acc += __shfl_xor_sync(0xffffffffu, acc, off);

    int lane = threadIdx.x & 31;
    int warp = threadIdx.x >> 5;
    if (lane == 0) warpsum[warp] = acc;
    __syncthreads();

    if (threadIdx.x == 0) {
        float bsum = 0.0f;
        #pragma unroll
        for (int w = 0; w < 8; w++) bsum += warpsum[w];
        g_partial[blockIdx.x] = bsum;
        __threadfence();
        unsigned int v = atomicAdd(&g_ticket, 1u);
        s_islast = (v == gridDim.x - 1) ? 1 : 0;
    }
    __syncthreads();

    // ---- last block reduces all partials (float tree; rel err ~1e-6) ----
    if (s_islast) {
        float d = 0.0f;
        for (int i = threadIdx.x; i < gridDim.x; i += blockDim.x)
            d += __ldcg(&g_partial[i]);   // L1-bypass: see peers' writes
        #pragma unroll
        for (int off = 16; off > 0; off >>= 1)
            d += __shfl_xor_sync(0xffffffffu, d, off);
        if (lane == 0) warpsum[warp] = d;
        __syncthreads();
        if (threadIdx.x == 0) {
            float tot = 0.0f;
            #pragma unroll
            for (int w = 0; w < 8; w++) tot += warpsum[w];
            out[0] = tot * invN;
            g_ticket = 0;   // reset for next graph replay
        }
    }
}

extern "C" void kernel_launch(void* const* d_in, const int* in_sizes, int n_in,
                              void* d_out, int out_size) {
    const float* pred = (const float*)d_in[0];
    const float* tru  = (const float*)d_in[1];
    const int*   ot   = (const int*)d_in[2];
    float* out = (float*)d_out;

    int B = in_sizes[0] / 3;
    int ngroups = B / 4;

    int threads = 256;
    int blocks = (ngroups + threads - 1) / threads;
    if (blocks < 1) blocks = 1;
    if (blocks > MAX_BLOCKS) blocks = MAX_BLOCKS;

    loss_kernel<<<blocks, threads>>>(pred, tru, ot, ngroups, B, out,
                                     1.0f / (float)B);
}

// round 5
// speedup vs baseline: 1.1641x; 1.0482x over previous
#include <cuda_runtime.h>
#include <cuda_fp16.h>

// ---------------------------------------------------------------------------
// weighted_loss over B=4.2M rows x 3 tasks. Single launch, threadfence
// reduction. Instruction-diet version:
//  - AIS counting in packed half2 (pred,true lanes together): 5 HSET2 + 4 HADD2
//  - w_cls = 1.1^|dAIS| via ex2.approx (no shared LUT, no LDS)
//  - w_mid via saturate identity: 1 + sat(yt/a) - sat((yt-b)/(c-b)), one
//    select for the >d exp tail; exp by 3-FMA Horner (arg in [-0.22,0])
//  - chest thresholds: scale data by rcp(s) instead of 5 threshold muls
// ---------------------------------------------------------------------------

#define MAX_BLOCKS 8192

__device__ float g_partial[MAX_BLOCKS];
__device__ unsigned int g_ticket = 0;   // returns to 0 each call -> deterministic

__device__ __forceinline__ __half2 h2c(unsigned short u) {
    __half2_raw r; r.x = u; r.y = u;
    return *reinterpret_cast<__half2*>(&r);
}

__device__ __forceinline__ float ex2_approx(float x) {
    float r;
    asm("ex2.approx.f32 %0, %1;" : "=f"(r) : "f"(x));
    return r;
}

__device__ __forceinline__ float rcp_approx(float x) {
    float r;
    asm("rcp.approx.f32 %0, %1;" : "=f"(r) : "f"(x));
    return r;
}

// exp(u) for u in [-0.23, 0.7], degree-3 Horner. abs err < 1e-4 on range.
__device__ __forceinline__ float exp3(float u) {
    float h = fmaf(u, 0.16666667f, 0.5f);
    h = fmaf(u, h, 1.0f);
    return fmaf(u, h, 1.0f);
}

// w_cls = 1.1^|ais(p)-ais(t)|, (p,t) packed in half2 vs 5 broadcast thresholds
__device__ __forceinline__ float wcls5(__half2 pt, __half2 a0, __half2 a1,
                                       __half2 a2, __half2 a3, __half2 a4) {
    __half2 acc = __hge2(pt, a0);
    acc = __hadd2(acc, __hge2(pt, a1));
    acc = __hadd2(acc, __hge2(pt, a2));
    acc = __hadd2(acc, __hge2(pt, a3));
    acc = __hadd2(acc, __hge2(pt, a4));
    float2 f = __half22float2(acc);
    float d = fabsf(f.x - f.y);
    return ex2_approx(d * 0.13750352f);   // log2(1.1)
}

// w_mid = 1 + piecewise(yt) [+1 if yp<0], via saturate identity.
// nb = -b/(c-b); neg_k = -ln2/d (so -k*(yt-d) = ln2 + neg_k*yt).
__device__ __forceinline__ float wmid_f(float yt, float yp,
                                        float d, float inv_a,
                                        float inv_cb, float nb, float neg_k) {
    float s1 = __saturatef(yt * inv_a);
    float s2 = __saturatef(fmaf(yt, inv_cb, nb));
    float w  = (1.0f - s2) + s1;
    float e  = exp3(fmaf(neg_k, yt, 0.69314718f));
    w = (yt > d) ? e : w;
    w += (yp < 0.0f) ? 1.0f : 0.0f;
    return w;
}

__device__ __forceinline__ float row_loss(float ph, float pd, float pn,
                                          float th, float td, float tn,
                                          int o) {
    // ---- head: thr {150,500,1000,1800,2600} (fp16-exact)
    float wch = wcls5(__floats2half2_rn(ph, th),
                      h2c(0x58B0), h2c(0x5FD0), h2c(0x63D0),
                      h2c(0x6708), h2c(0x6914));
    float mh = wmid_f(th, ph, 2000.0f, 0.0125f, 0.004f, -6.0f, -3.4657359e-4f);
    float L = fabsf(ph - th) * wch * mh;

    // ---- chest: thr {22,35,45,55,65}*s  <=>  (x/s) vs thr
    float s = fmaf(0.1f, (float)o, 0.8f);
    float is = rcp_approx(s);
    __half2 is2 = __half2half2(__float2half_rn(is));
    float wcc = wcls5(__hmul2(__floats2half2_rn(pd, td), is2),
                      h2c(0x4D80), h2c(0x5060), h2c(0x51A0),
                      h2c(0x52E0), h2c(0x5410));
    float mc = wmid_f(td, pd, 100.0f, 0.1f, 0.1f, -7.5f, -6.9314718e-3f);
    L += fabsf(pd - td) * wcc * mc;

    // ---- neck: thr {0.2,0.5,1.0,1.5,2.0}
    float wcn = wcls5(__floats2half2_rn(pn, tn),
                      h2c(0x3266), h2c(0x3800), h2c(0x3C00),
                      h2c(0x3E00), h2c(0x4000));
    float mn = wmid_f(tn, pn, 1.9f, 6.6666667f, 5.0f, -7.5f, -0.36481431f);
    L += fabsf(pn - tn) * wcn * mn;

    return L;
}

__global__ void __launch_bounds__(256, 6)
loss_kernel(const float* __restrict__ pred,
            const float* __restrict__ tru,
            const int* __restrict__ ot,
            int ngroups, int nrows,
            float* __restrict__ out, float invN) {
    __shared__ float warpsum[8];
    __shared__ int s_islast;

    const float4* __restrict__ pv = (const float4*)pred;
    const float4* __restrict__ tv = (const float4*)tru;
    const int4* __restrict__ ov = (const int4*)ot;

    int tid = blockIdx.x * blockDim.x + threadIdx.x;
    int stride = gridDim.x * blockDim.x;

    float acc = 0.0f;
    for (int g = tid; g < ngroups; g += stride) {
        float4 p0 = pv[3 * g + 0];
        float4 p1 = pv[3 * g + 1];
        float4 p2 = pv[3 * g + 2];
        float4 t0 = tv[3 * g + 0];
        float4 t1 = tv[3 * g + 1];
        float4 t2 = tv[3 * g + 2];
        int4 o = ov[g];
        acc += row_loss(p0.x, p0.y, p0.z, t0.x, t0.y, t0.z, o.x);
        acc += row_loss(p0.w, p1.x, p1.y, t0.w, t1.x, t1.y, o.y);
        acc += row_loss(p1.z, p1.w, p2.x, t1.z, t1.w, t2.x, o.z);
        acc += row_loss(p2.y, p2.z, p2.w, t2.y, t2.z, t2.w, o.w);
    }
    // tail rows (B % 4 != 0 -- not hit for B=4194304)
    for (int r = 4 * ngroups + tid; r < nrows; r += stride) {
        acc += row_loss(pred[3 * r + 0], pred[3 * r + 1], pred[3 * r + 2],
                        tru[3 * r + 0], tru[3 * r + 1], tru[3 * r + 2], ot[r]);
    }

    // ---- block reduce (float) ----
    #pragma unroll
    for (int off = 16; off > 0; off >>= 1)
        acc += __shfl_xor_sync(0xffffffffu, acc, off);

    int lane = threadIdx.x & 31;
    int warp = threadIdx.x >> 5;
    if (lane == 0) warpsum[warp] = acc;
    __syncthreads();

    if (threadIdx.x == 0) {
        float bsum = 0.0f;
        #pragma unroll
        for (int w = 0; w < 8; w++) bsum += warpsum[w];
        g_partial[blockIdx.x] = bsum;
        __threadfence();
        unsigned int v = atomicAdd(&g_ticket, 1u);
        s_islast = (v == gridDim.x - 1) ? 1 : 0;
    }
    __syncthreads();

    // ---- last block reduces all partials ----
    if (s_islast) {
        float d = 0.0f;
        for (int i = threadIdx.x; i < gridDim.x; i += blockDim.x)
            d += __ldcg(&g_partial[i]);
        #pragma unroll
        for (int off = 16; off > 0; off >>= 1)
            d += __shfl_xor_sync(0xffffffffu, d, off);
        if (lane == 0) warpsum[warp] = d;
        __syncthreads();
        if (threadIdx.x == 0) {
            float tot = 0.0f;
            #pragma unroll
            for (int w = 0; w < 8; w++) tot += warpsum[w];
            out[0] = tot * invN;
            g_ticket = 0;   // reset for next graph replay
        }
    }
}

extern "C" void kernel_launch(void* const* d_in, const int* in_sizes, int n_in,
                              void* d_out, int out_size) {
    const float* pred = (const float*)d_in[0];
    const float* tru  = (const float*)d_in[1];
    const int*   ot   = (const int*)d_in[2];
    float* out = (float*)d_out;

    int B = in_sizes[0] / 3;
    int ngroups = B / 4;

    int threads = 256;
    int blocks = (ngroups + threads - 1) / threads;
    if (blocks < 1) blocks = 1;
    if (blocks > MAX_BLOCKS) blocks = MAX_BLOCKS;

    loss_kernel<<<blocks, threads>>>(pred, tru, ot, ngroups, B, out,
                                     1.0f / (float)B);
}

// round 6
// speedup vs baseline: 1.4477x; 1.2436x over previous
#include <cuda_runtime.h>
#include <cuda_fp16.h>

// ---------------------------------------------------------------------------
// weighted_loss over B=4.2M rows x 3 tasks. PERSISTENT single-wave grid:
// 912 blocks = 152 SMs x 6 CTAs, grid-stride loop (~4-5 groups/thread).
// Kills wave transitions, 4.6x wave ramp (front-batched LDG L1tex contention),
// and 4096->912 CTA reduce tails. Compute path: half2 AIS counting,
// ex2.approx for 1.1^n, saturate-identity wmid, 3-FMA exp tail.
// ---------------------------------------------------------------------------

#define MAX_BLOCKS 2048

__device__ float g_partial[MAX_BLOCKS];
__device__ unsigned int g_ticket = 0;   // returns to 0 each call -> deterministic

__device__ __forceinline__ __half2 h2c(unsigned short u) {
    __half2_raw r; r.x = u; r.y = u;
    return *reinterpret_cast<__half2*>(&r);
}

__device__ __forceinline__ float ex2_approx(float x) {
    float r;
    asm("ex2.approx.f32 %0, %1;" : "=f"(r) : "f"(x));
    return r;
}

__device__ __forceinline__ float rcp_approx(float x) {
    float r;
    asm("rcp.approx.f32 %0, %1;" : "=f"(r) : "f"(x));
    return r;
}

// exp(u) for u in [-0.23, 0.7], degree-3 Horner. abs err < 1e-4 on range.
__device__ __forceinline__ float exp3(float u) {
    float h = fmaf(u, 0.16666667f, 0.5f);
    h = fmaf(u, h, 1.0f);
    return fmaf(u, h, 1.0f);
}

// w_cls = 1.1^|ais(p)-ais(t)|, (p,t) packed in half2 vs 5 broadcast thresholds
__device__ __forceinline__ float wcls5(__half2 pt, __half2 a0, __half2 a1,
                                       __half2 a2, __half2 a3, __half2 a4) {
    __half2 acc = __hge2(pt, a0);
    acc = __hadd2(acc, __hge2(pt, a1));
    acc = __hadd2(acc, __hge2(pt, a2));
    acc = __hadd2(acc, __hge2(pt, a3));
    acc = __hadd2(acc, __hge2(pt, a4));
    float2 f = __half22float2(acc);
    float d = fabsf(f.x - f.y);
    return ex2_approx(d * 0.13750352f);   // log2(1.1)
}

// w_mid = 1 + piecewise(yt) [+1 if yp<0], via saturate identity.
// nb = -b/(c-b); neg_k = -ln2/d (so -k*(yt-d) = ln2 + neg_k*yt).
__device__ __forceinline__ float wmid_f(float yt, float yp,
                                        float d, float inv_a,
                                        float inv_cb, float nb, float neg_k) {
    float s1 = __saturatef(yt * inv_a);
    float s2 = __saturatef(fmaf(yt, inv_cb, nb));
    float w  = (1.0f - s2) + s1;
    float e  = exp3(fmaf(neg_k, yt, 0.69314718f));
    w = (yt > d) ? e : w;
    w += (yp < 0.0f) ? 1.0f : 0.0f;
    return w;
}

__device__ __forceinline__ float row_loss(float ph, float pd, float pn,
                                          float th, float td, float tn,
                                          int o) {
    // ---- head: thr {150,500,1000,1800,2600} (fp16-exact)
    float wch = wcls5(__floats2half2_rn(ph, th),
                      h2c(0x58B0), h2c(0x5FD0), h2c(0x63D0),
                      h2c(0x6708), h2c(0x6914));
    float mh = wmid_f(th, ph, 2000.0f, 0.0125f, 0.004f, -6.0f, -3.4657359e-4f);
    float L = fabsf(ph - th) * wch * mh;

    // ---- chest: thr {22,35,45,55,65}*s  <=>  (x/s) vs thr
    float s = fmaf(0.1f, (float)o, 0.8f);
    float is = rcp_approx(s);
    __half2 is2 = __half2half2(__float2half_rn(is));
    float wcc = wcls5(__hmul2(__floats2half2_rn(pd, td), is2),
                      h2c(0x4D80), h2c(0x5060), h2c(0x51A0),
                      h2c(0x52E0), h2c(0x5410));
    float mc = wmid_f(td, pd, 100.0f, 0.1f, 0.1f, -7.5f, -6.9314718e-3f);
    L += fabsf(pd - td) * wcc * mc;

    // ---- neck: thr {0.2,0.5,1.0,1.5,2.0}
    float wcn = wcls5(__floats2half2_rn(pn, tn),
                      h2c(0x3266), h2c(0x3800), h2c(0x3C00),
                      h2c(0x3E00), h2c(0x4000));
    float mn = wmid_f(tn, pn, 1.9f, 6.6666667f, 5.0f, -7.5f, -0.36481431f);
    L += fabsf(pn - tn) * wcn * mn;

    return L;
}

__global__ void __launch_bounds__(256, 6)
loss_kernel(const float* __restrict__ pred,
            const float* __restrict__ tru,
            const int* __restrict__ ot,
            int ngroups, int nrows,
            float* __restrict__ out, float invN) {
    __shared__ float warpsum[8];
    __shared__ int s_islast;

    const float4* __restrict__ pv = (const float4*)pred;
    const float4* __restrict__ tv = (const float4*)tru;
    const int4* __restrict__ ov = (const int4*)ot;

    int tid = blockIdx.x * blockDim.x + threadIdx.x;
    int stride = gridDim.x * blockDim.x;

    float acc = 0.0f;
    #pragma unroll 1
    for (int g = tid; g < ngroups; g += stride) {
        float4 p0 = pv[3 * g + 0];
        float4 p1 = pv[3 * g + 1];
        float4 p2 = pv[3 * g + 2];
        float4 t0 = tv[3 * g + 0];
        float4 t1 = tv[3 * g + 1];
        float4 t2 = tv[3 * g + 2];
        int4 o = ov[g];
        acc += row_loss(p0.x, p0.y, p0.z, t0.x, t0.y, t0.z, o.x);
        acc += row_loss(p0.w, p1.x, p1.y, t0.w, t1.x, t1.y, o.y);
        acc += row_loss(p1.z, p1.w, p2.x, t1.z, t1.w, t2.x, o.z);
        acc += row_loss(p2.y, p2.z, p2.w, t2.y, t2.z, t2.w, o.w);
    }
    // tail rows (B % 4 != 0 -- not hit for B=4194304)
    for (int r = 4 * ngroups + tid; r < nrows; r += stride) {
        acc += row_loss(pred[3 * r + 0], pred[3 * r + 1], pred[3 * r + 2],
                        tru[3 * r + 0], tru[3 * r + 1], tru[3 * r + 2], ot[r]);
    }

    // ---- block reduce (float) ----
    #pragma unroll
    for (int off = 16; off > 0; off >>= 1)
        acc += __shfl_xor_sync(0xffffffffu, acc, off);

    int lane = threadIdx.x & 31;
    int warp = threadIdx.x >> 5;
    if (lane == 0) warpsum[warp] = acc;
    __syncthreads();

    if (threadIdx.x == 0) {
        float bsum = 0.0f;
        #pragma unroll
        for (int w = 0; w < 8; w++) bsum += warpsum[w];
        g_partial[blockIdx.x] = bsum;
        __threadfence();
        unsigned int v = atomicAdd(&g_ticket, 1u);
        s_islast = (v == gridDim.x - 1) ? 1 : 0;
    }
    __syncthreads();

    // ---- last block reduces all partials ----
    if (s_islast) {
        float d = 0.0f;
        for (int i = threadIdx.x; i < gridDim.x; i += blockDim.x)
            d += __ldcg(&g_partial[i]);
        #pragma unroll
        for (int off = 16; off > 0; off >>= 1)
            d += __shfl_xor_sync(0xffffffffu, d, off);
        if (lane == 0) warpsum[warp] = d;
        __syncthreads();
        if (threadIdx.x == 0) {
            float tot = 0.0f;
            #pragma unroll
            for (int w = 0; w < 8; w++) tot += warpsum[w];
            out[0] = tot * invN;
            g_ticket = 0;   // reset for next graph replay
        }
    }
}

extern "C" void kernel_launch(void* const* d_in, const int* in_sizes, int n_in,
                              void* d_out, int out_size) {
    const float* pred = (const float*)d_in[0];
    const float* tru  = (const float*)d_in[1];
    const int*   ot   = (const int*)d_in[2];
    float* out = (float*)d_out;

    int B = in_sizes[0] / 3;
    int ngroups = B / 4;

    // Persistent single wave: 152 SMs x 6 CTAs/SM
    int threads = 256;
    int blocks = 912;
    int maxb = (ngroups + threads - 1) / threads;
    if (blocks > maxb) blocks = maxb;
    if (blocks < 1) blocks = 1;
    if (blocks > MAX_BLOCKS) blocks = MAX_BLOCKS;

    loss_kernel<<<blocks, threads>>>(pred, tru, ot, ngroups, B, out,
                                     1.0f / (float)B);
}